// round 10
// baseline (speedup 1.0000x reference)
#include <cuda_runtime.h>
#include <cuda_fp16.h>
#include <cstdint>

#define T_STEPS 16
#define BLK 256
#define EPB 256            // 8 warps x 32 batch rows per warp

__device__ __forceinline__ float tanh_ap(float x) {
    float y; asm("tanh.approx.f32 %0, %1;" : "=f"(y) : "f"(x)); return y;
}
__device__ __forceinline__ float sigm(float x) {
    return fmaf(tanh_ap(0.5f * x), 0.5f, 0.5f);
}
__device__ __forceinline__ float softplus_(float x) {
    return fmaxf(x, 0.0f) + log1pf(__expf(-fabsf(x)));   // exact: sets rel_err
}
__device__ __forceinline__ unsigned packh2(float a, float b) {
    __half2 h = __floats2half2_rn(a, b);
    return *(unsigned*)&h;
}

// D = A(16x16 f16) @ B(16x8 f16) + C (f32), row.col
__device__ __forceinline__ void mma16816(float* c, const unsigned* a, const unsigned* b) {
    asm volatile("mma.sync.aligned.m16n8k16.row.col.f32.f16.f16.f32 "
                 "{%0,%1,%2,%3}, {%4,%5,%6,%7}, {%8,%9}, {%0,%1,%2,%3};"
                 : "+f"(c[0]), "+f"(c[1]), "+f"(c[2]), "+f"(c[3])
                 : "r"(a[0]), "r"(a[1]), "r"(a[2]), "r"(a[3]), "r"(b[0]), "r"(b[1]));
}

__global__ void __launch_bounds__(BLK)
flow_mma_kernel(const float* __restrict__ x, const float* __restrict__ z,
                const float* __restrict__ W_ih, const float* __restrict__ W_hh,
                const float* __restrict__ b_ih, const float* __restrict__ b_hh,
                const float* __restrict__ W1, const float* __restrict__ b1,
                const float* __restrict__ W2, const float* __restrict__ b2,
                float* __restrict__ out, int Btot)
{
    __shared__ __half whh_h[192 * 64];   // [j][k] row-major
    __shared__ __half w1t_h[32 * 64];    // [m][k] (W1 transposed)
    __shared__ __half w2t_h[8 * 32];     // [n][k] (W2 transposed, n padded to 8)
    __shared__ float4 giw_s[192];        // {wih0, wih1, bias, bhh_n}
    __shared__ float  b1_s[32];
    __shared__ float  b2_s[8];           // padded

    const int tid = threadIdx.x;

    // ---- stage weights (fp16) ----
    for (int i = tid; i < 12288; i += BLK) whh_h[i] = __float2half_rn(W_hh[i]);
    for (int i = tid; i < 2048; i += BLK) {
        int m = i >> 6, k = i & 63;
        w1t_h[i] = __float2half_rn(W1[k * 32 + m]);
    }
    for (int i = tid; i < 256; i += BLK) {
        int n = i >> 5, k = i & 31;
        w2t_h[i] = (n < 4) ? __float2half_rn(W2[k * 4 + n]) : __float2half_rn(0.0f);
    }
    for (int j = tid; j < 192; j += BLK) {
        float bi = b_ih[j], bh = b_hh[j];
        giw_s[j] = (j < 128) ? make_float4(W_ih[2 * j], W_ih[2 * j + 1], bi + bh, 0.0f)
                             : make_float4(W_ih[2 * j], W_ih[2 * j + 1], bi, bh);
    }
    if (tid < 32) b1_s[tid] = b1[tid];
    if (tid < 8)  b2_s[tid] = (tid < 4) ? b2[tid] : 0.0f;
    __syncthreads();

    const int wid = tid >> 5, lid = tid & 31;
    const int qr = lid >> 2, qc = lid & 3;
    const int rowbase = blockIdx.x * EPB + wid * 32;   // warp's first batch row
    const bool owner = (qc == 0);

    // ---- A fragments = h (init from z), [Mtile][ktile][reg], f16x2 ----
    unsigned A[2][4][4];
    #pragma unroll
    for (int mt = 0; mt < 2; ++mt)
        #pragma unroll
        for (int kt = 0; kt < 4; ++kt)
            #pragma unroll
            for (int rg = 0; rg < 4; ++rg) {
                int row = rowbase + 16 * mt + qr + 8 * (rg & 1);
                int k = 2 * qc + 8 * (rg >> 1) + 16 * kt;
                float2 v = *(const float2*)(z + (size_t)row * 64 + k);
                A[mt][kt][rg] = packh2(v.x, v.y);
            }

    // owner-lane per-row state: rows rowbase + qr + 8*yi, yi = 0..3
    float yown[8] = {0.f, 0.f, 0.f, 0.f, 0.f, 0.f, 0.f, 0.f};
    float pown[8] = {1.f, 1.f, 1.f, 1.f, 1.f, 1.f, 1.f, 1.f};

    #pragma unroll 1
    for (int t = 0; t < T_STEPS; ++t) {
        // broadcast y_prev of the 4 rows this lane epilogues (owner lane = 4*qr)
        float yp[8];
        #pragma unroll
        for (int yi = 0; yi < 4; ++yi) {
            yp[2 * yi]     = __shfl_sync(0xffffffffu, yown[2 * yi],     4 * qr);
            yp[2 * yi + 1] = __shfl_sync(0xffffffffu, yown[2 * yi + 1], 4 * qr);
        }
        // x_t for the quad's rows (same address across quad -> dedup'd)
        float2 xo[4];
        #pragma unroll
        for (int yi = 0; yi < 4; ++yi)
            xo[yi] = *(const float2*)(x + (size_t)(rowbase + qr + 8 * yi) * 32 + 2 * t);

        // ---- GRU: gh = h @ W_hh^T via HMMA, gates in epilogue ----
        unsigned Anew[2][4][4];
        #pragma unroll
        for (int jt = 0; jt < 8; ++jt) {
            float c[3][2][4];
            #pragma unroll
            for (int g = 0; g < 3; ++g)
                #pragma unroll
                for (int mt = 0; mt < 2; ++mt)
                    #pragma unroll
                    for (int i = 0; i < 4; ++i) c[g][mt][i] = 0.f;

            #pragma unroll
            for (int kt = 0; kt < 4; ++kt)
                #pragma unroll
                for (int g = 0; g < 3; ++g) {
                    int j = 8 * (jt + 8 * g) + qr;      // B col n = qr
                    unsigned b[2];
                    b[0] = *(const unsigned*)(whh_h + j * 64 + 16 * kt + 2 * qc);
                    b[1] = *(const unsigned*)(whh_h + j * 64 + 16 * kt + 2 * qc + 8);
                    mma16816(c[g][0], A[0][kt], b);
                    mma16816(c[g][1], A[1][kt], b);
                }

            const int j0 = 8 * jt + 2 * qc;
            const float4 gr0 = giw_s[j0],       gr1 = giw_s[j0 + 1];
            const float4 gz0 = giw_s[64 + j0],  gz1 = giw_s[64 + j0 + 1];
            const float4 gn0 = giw_s[128 + j0], gn1 = giw_s[128 + j0 + 1];

            #pragma unroll
            for (int mt = 0; mt < 2; ++mt)
                #pragma unroll
                for (int hf = 0; hf < 2; ++hf) {
                    const int yi = hf + 2 * mt;
                    const float y0 = yp[2 * yi], y1 = yp[2 * yi + 1];
                    // col 0
                    float r0 = sigm(fmaf(y1, gr0.y, fmaf(y0, gr0.x, gr0.z)) + c[0][mt][2 * hf]);
                    float u0 = sigm(fmaf(y1, gz0.y, fmaf(y0, gz0.x, gz0.z)) + c[1][mt][2 * hf]);
                    float n0 = tanh_ap(fmaf(r0, c[2][mt][2 * hf] + gn0.w,
                                            fmaf(y1, gn0.y, fmaf(y0, gn0.x, gn0.z))));
                    // col 1
                    float r1 = sigm(fmaf(y1, gr1.y, fmaf(y0, gr1.x, gr1.z)) + c[0][mt][2 * hf + 1]);
                    float u1 = sigm(fmaf(y1, gz1.y, fmaf(y0, gz1.x, gz1.z)) + c[1][mt][2 * hf + 1]);
                    float n1 = tanh_ap(fmaf(r1, c[2][mt][2 * hf + 1] + gn1.w,
                                            fmaf(y1, gn1.y, fmaf(y0, gn1.x, gn1.z))));
                    // hold = old h at same fragment slot
                    unsigned au = A[mt][jt >> 1][(jt & 1) * 2 + hf];
                    __half2 hh = *(__half2*)&au;
                    float h0 = fmaf(u0, __half2float(hh.x) - n0, n0);
                    float h1 = fmaf(u1, __half2float(hh.y) - n1, n1);
                    Anew[mt][jt >> 1][(jt & 1) * 2 + hf] = packh2(h0, h1);
                }
        }
        // commit h_new
        #pragma unroll
        for (int mt = 0; mt < 2; ++mt)
            #pragma unroll
            for (int kt = 0; kt < 4; ++kt)
                #pragma unroll
                for (int rg = 0; rg < 4; ++rg) A[mt][kt][rg] = Anew[mt][kt][rg];

        // ---- MLP1: hid = relu(h_new @ W1 + b1) via HMMA ----
        float ch[2][4][4];
        #pragma unroll
        for (int mt = 0; mt < 2; ++mt)
            #pragma unroll
            for (int nt = 0; nt < 4; ++nt)
                #pragma unroll
                for (int i = 0; i < 4; ++i) ch[mt][nt][i] = 0.f;
        #pragma unroll
        for (int kt = 0; kt < 4; ++kt)
            #pragma unroll
            for (int nt = 0; nt < 4; ++nt) {
                int m = 8 * nt + qr;
                unsigned b[2];
                b[0] = *(const unsigned*)(w1t_h + m * 64 + 16 * kt + 2 * qc);
                b[1] = *(const unsigned*)(w1t_h + m * 64 + 16 * kt + 2 * qc + 8);
                mma16816(ch[0][nt], A[0][kt], b);
                mma16816(ch[1][nt], A[1][kt], b);
            }
        // relu + bias, repack as A2 fragments (k = m)
        unsigned A2[2][2][4];
        #pragma unroll
        for (int nt = 0; nt < 4; ++nt) {
            float2 b1v = *(const float2*)(b1_s + 8 * nt + 2 * qc);
            #pragma unroll
            for (int mt = 0; mt < 2; ++mt)
                #pragma unroll
                for (int hf = 0; hf < 2; ++hf) {
                    float v0 = fmaxf(ch[mt][nt][2 * hf]     + b1v.x, 0.f);
                    float v1 = fmaxf(ch[mt][nt][2 * hf + 1] + b1v.y, 0.f);
                    A2[mt][nt >> 1][(nt & 1) * 2 + hf] = packh2(v0, v1);
                }
        }
        // ---- MLP2: ls = hid @ W2 + b2 (N padded to 8) ----
        float cl[2][4];
        #pragma unroll
        for (int mt = 0; mt < 2; ++mt)
            #pragma unroll
            for (int i = 0; i < 4; ++i) cl[mt][i] = 0.f;
        #pragma unroll
        for (int kt = 0; kt < 2; ++kt) {
            unsigned b[2];
            b[0] = *(const unsigned*)(w2t_h + qr * 32 + 16 * kt + 2 * qc);
            b[1] = *(const unsigned*)(w2t_h + qr * 32 + 16 * kt + 2 * qc + 8);
            mma16816(cl[0], A2[0][kt], b);
            mma16816(cl[1], A2[1][kt], b);
        }
        // head: qc==0 lanes hold (ls0,ls1)=dloc, qc==1 lanes hold (ls2,ls3)->scale
        float2 b2v = *(const float2*)(b2_s + 2 * qc);
        #pragma unroll
        for (int mt = 0; mt < 2; ++mt)
            #pragma unroll
            for (int hf = 0; hf < 2; ++hf) {
                const int yi = hf + 2 * mt;
                float v0 = cl[mt][2 * hf]     + b2v.x;
                float v1 = cl[mt][2 * hf + 1] + b2v.y;
                float sp0 = softplus_(v0) + 0.001f;
                float sp1 = softplus_(v1) + 0.001f;
                float s0 = __shfl_sync(0xffffffffu, sp0, (lid & ~3) | 1);
                float s1 = __shfl_sync(0xffffffffu, sp1, (lid & ~3) | 1);
                if (owner) {
                    float yn0 = yown[2 * yi]     + v0 + s0 * xo[yi].x;
                    float yn1 = yown[2 * yi + 1] + v1 + s1 * xo[yi].y;
                    yown[2 * yi] = yn0; yown[2 * yi + 1] = yn1;
                    pown[2 * yi] *= s0; pown[2 * yi + 1] *= s1;
                    int rowg = rowbase + qr + 8 * yi;
                    *(float2*)(out + (size_t)rowg * 32 + 2 * t) = make_float2(yn0, yn1);
                }
            }
    }

    if (owner) {
        #pragma unroll
        for (int yi = 0; yi < 4; ++yi) {
            int rowg = rowbase + qr + 8 * yi;
            out[(size_t)Btot * 32 + rowg] =
                logf(fabsf(pown[2 * yi])) + logf(fabsf(pown[2 * yi + 1]));
        }
    }
}

extern "C" void kernel_launch(void* const* d_in, const int* in_sizes, int n_in,
                              void* d_out, int out_size)
{
    const float* x    = (const float*)d_in[0];
    const float* z    = (const float*)d_in[1];
    const float* W_ih = (const float*)d_in[2];
    const float* W_hh = (const float*)d_in[3];
    const float* b_ih = (const float*)d_in[4];
    const float* b_hh = (const float*)d_in[5];
    const float* W1   = (const float*)d_in[6];
    const float* b1   = (const float*)d_in[7];
    const float* W2   = (const float*)d_in[8];
    const float* b2   = (const float*)d_in[9];

    int B = in_sizes[1] / 64;   // z is (B, 64)

    flow_mma_kernel<<<B / EPB, BLK>>>(
        x, z, W_ih, W_hh, b_ih, b_hh, W1, b1, W2, b2, (float*)d_out, B);
}

// round 11
// speedup vs baseline: 1.0010x; 1.0010x over previous
#include <cuda_runtime.h>
#include <cuda_fp16.h>
#include <cstdint>

#define T_STEPS 16
#define BLK 256
#define EPB 256            // 8 warps x 32 batch rows per warp

__device__ __forceinline__ float tanh_ap(float x) {
    float y; asm("tanh.approx.f32 %0, %1;" : "=f"(y) : "f"(x)); return y;
}
__device__ __forceinline__ float sigm(float x) {
    return fmaf(tanh_ap(0.5f * x), 0.5f, 0.5f);
}
__device__ __forceinline__ float softplus_(float x) {
    return fmaxf(x, 0.0f) + log1pf(__expf(-fabsf(x)));   // exact: sets rel_err
}
__device__ __forceinline__ unsigned packh2(float a, float b) {
    __half2 h = __floats2half2_rn(a, b);
    return *(unsigned*)&h;
}

// D = A(16x16 f16) @ B(16x8 f16) + C (f32), row.col
__device__ __forceinline__ void mma16816(float* c, const unsigned* a, const unsigned* b) {
    asm volatile("mma.sync.aligned.m16n8k16.row.col.f32.f16.f16.f32 "
                 "{%0,%1,%2,%3}, {%4,%5,%6,%7}, {%8,%9}, {%0,%1,%2,%3};"
                 : "+f"(c[0]), "+f"(c[1]), "+f"(c[2]), "+f"(c[3])
                 : "r"(a[0]), "r"(a[1]), "r"(a[2]), "r"(a[3]), "r"(b[0]), "r"(b[1]));
}

__global__ void __launch_bounds__(BLK)
flow_mma_kernel(const float* __restrict__ x, const float* __restrict__ z,
                const float* __restrict__ W_ih, const float* __restrict__ W_hh,
                const float* __restrict__ b_ih, const float* __restrict__ b_hh,
                const float* __restrict__ W1, const float* __restrict__ b1,
                const float* __restrict__ W2, const float* __restrict__ b2,
                float* __restrict__ out, int Btot)
{
    __shared__ __half whh_h[192 * 64];   // [j][k] row-major
    __shared__ __half w1t_h[32 * 64];    // [m][k] (W1 transposed)
    __shared__ __half w2t_h[8 * 32];     // [n][k] (W2 transposed, n padded to 8)
    __shared__ float4 giw_s[192];        // {wih0, wih1, bias, bhh_n}
    __shared__ float  b1_s[32];
    __shared__ float  b2_s[8];           // padded

    const int tid = threadIdx.x;

    // ---- stage weights (fp16) ----
    for (int i = tid; i < 12288; i += BLK) whh_h[i] = __float2half_rn(W_hh[i]);
    for (int i = tid; i < 2048; i += BLK) {
        int m = i >> 6, k = i & 63;
        w1t_h[i] = __float2half_rn(W1[k * 32 + m]);
    }
    for (int i = tid; i < 256; i += BLK) {
        int n = i >> 5, k = i & 31;
        w2t_h[i] = (n < 4) ? __float2half_rn(W2[k * 4 + n]) : __float2half_rn(0.0f);
    }
    for (int j = tid; j < 192; j += BLK) {
        float bi = b_ih[j], bh = b_hh[j];
        giw_s[j] = (j < 128) ? make_float4(W_ih[2 * j], W_ih[2 * j + 1], bi + bh, 0.0f)
                             : make_float4(W_ih[2 * j], W_ih[2 * j + 1], bi, bh);
    }
    if (tid < 32) b1_s[tid] = b1[tid];
    if (tid < 8)  b2_s[tid] = (tid < 4) ? b2[tid] : 0.0f;
    __syncthreads();

    const int wid = tid >> 5, lid = tid & 31;
    const int qr = lid >> 2, qc = lid & 3;
    const int rowbase = blockIdx.x * EPB + wid * 32;   // warp's first batch row
    const bool owner = (qc == 0);

    // ---- A fragments = h (init from z), [Mtile][ktile][reg], f16x2 ----
    unsigned A[2][4][4];
    #pragma unroll
    for (int mt = 0; mt < 2; ++mt)
        #pragma unroll
        for (int kt = 0; kt < 4; ++kt)
            #pragma unroll
            for (int rg = 0; rg < 4; ++rg) {
                int row = rowbase + 16 * mt + qr + 8 * (rg & 1);
                int k = 2 * qc + 8 * (rg >> 1) + 16 * kt;
                float2 v = *(const float2*)(z + (size_t)row * 64 + k);
                A[mt][kt][rg] = packh2(v.x, v.y);
            }

    // owner-lane per-row state: rows rowbase + qr + 8*yi, yi = 0..3
    float yown[8] = {0.f, 0.f, 0.f, 0.f, 0.f, 0.f, 0.f, 0.f};
    float pown[8] = {1.f, 1.f, 1.f, 1.f, 1.f, 1.f, 1.f, 1.f};

    #pragma unroll 1
    for (int t = 0; t < T_STEPS; ++t) {
        // broadcast y_prev of the 4 rows this lane epilogues (owner lane = 4*qr)
        float yp[8];
        #pragma unroll
        for (int yi = 0; yi < 4; ++yi) {
            yp[2 * yi]     = __shfl_sync(0xffffffffu, yown[2 * yi],     4 * qr);
            yp[2 * yi + 1] = __shfl_sync(0xffffffffu, yown[2 * yi + 1], 4 * qr);
        }
        // x_t for the quad's rows (same address across quad -> dedup'd)
        float2 xo[4];
        #pragma unroll
        for (int yi = 0; yi < 4; ++yi)
            xo[yi] = *(const float2*)(x + (size_t)(rowbase + qr + 8 * yi) * 32 + 2 * t);

        // ---- GRU: gh = h @ W_hh^T via HMMA, gates in epilogue ----
        unsigned Anew[2][4][4];
        #pragma unroll
        for (int jt = 0; jt < 8; ++jt) {
            float c[3][2][4];
            #pragma unroll
            for (int g = 0; g < 3; ++g)
                #pragma unroll
                for (int mt = 0; mt < 2; ++mt)
                    #pragma unroll
                    for (int i = 0; i < 4; ++i) c[g][mt][i] = 0.f;

            #pragma unroll
            for (int kt = 0; kt < 4; ++kt)
                #pragma unroll
                for (int g = 0; g < 3; ++g) {
                    int j = 8 * (jt + 8 * g) + qr;      // B col n = qr
                    unsigned b[2];
                    b[0] = *(const unsigned*)(whh_h + j * 64 + 16 * kt + 2 * qc);
                    b[1] = *(const unsigned*)(whh_h + j * 64 + 16 * kt + 2 * qc + 8);
                    mma16816(c[g][0], A[0][kt], b);
                    mma16816(c[g][1], A[1][kt], b);
                }

            const int j0 = 8 * jt + 2 * qc;
            const float4 gr0 = giw_s[j0],       gr1 = giw_s[j0 + 1];
            const float4 gz0 = giw_s[64 + j0],  gz1 = giw_s[64 + j0 + 1];
            const float4 gn0 = giw_s[128 + j0], gn1 = giw_s[128 + j0 + 1];

            #pragma unroll
            for (int mt = 0; mt < 2; ++mt)
                #pragma unroll
                for (int hf = 0; hf < 2; ++hf) {
                    const int yi = hf + 2 * mt;
                    const float y0 = yp[2 * yi], y1 = yp[2 * yi + 1];
                    // col 0
                    float r0 = sigm(fmaf(y1, gr0.y, fmaf(y0, gr0.x, gr0.z)) + c[0][mt][2 * hf]);
                    float u0 = sigm(fmaf(y1, gz0.y, fmaf(y0, gz0.x, gz0.z)) + c[1][mt][2 * hf]);
                    float n0 = tanh_ap(fmaf(r0, c[2][mt][2 * hf] + gn0.w,
                                            fmaf(y1, gn0.y, fmaf(y0, gn0.x, gn0.z))));
                    // col 1
                    float r1 = sigm(fmaf(y1, gr1.y, fmaf(y0, gr1.x, gr1.z)) + c[0][mt][2 * hf + 1]);
                    float u1 = sigm(fmaf(y1, gz1.y, fmaf(y0, gz1.x, gz1.z)) + c[1][mt][2 * hf + 1]);
                    float n1 = tanh_ap(fmaf(r1, c[2][mt][2 * hf + 1] + gn1.w,
                                            fmaf(y1, gn1.y, fmaf(y0, gn1.x, gn1.z))));
                    // hold = old h at same fragment slot
                    unsigned au = A[mt][jt >> 1][(jt & 1) * 2 + hf];
                    __half2 hh = *(__half2*)&au;
                    float h0 = fmaf(u0, __half2float(hh.x) - n0, n0);
                    float h1 = fmaf(u1, __half2float(hh.y) - n1, n1);
                    Anew[mt][jt >> 1][(jt & 1) * 2 + hf] = packh2(h0, h1);
                }
        }
        // commit h_new
        #pragma unroll
        for (int mt = 0; mt < 2; ++mt)
            #pragma unroll
            for (int kt = 0; kt < 4; ++kt)
                #pragma unroll
                for (int rg = 0; rg < 4; ++rg) A[mt][kt][rg] = Anew[mt][kt][rg];

        // ---- MLP1: hid = relu(h_new @ W1 + b1) via HMMA ----
        float ch[2][4][4];
        #pragma unroll
        for (int mt = 0; mt < 2; ++mt)
            #pragma unroll
            for (int nt = 0; nt < 4; ++nt)
                #pragma unroll
                for (int i = 0; i < 4; ++i) ch[mt][nt][i] = 0.f;
        #pragma unroll
        for (int kt = 0; kt < 4; ++kt)
            #pragma unroll
            for (int nt = 0; nt < 4; ++nt) {
                int m = 8 * nt + qr;
                unsigned b[2];
                b[0] = *(const unsigned*)(w1t_h + m * 64 + 16 * kt + 2 * qc);
                b[1] = *(const unsigned*)(w1t_h + m * 64 + 16 * kt + 2 * qc + 8);
                mma16816(ch[0][nt], A[0][kt], b);
                mma16816(ch[1][nt], A[1][kt], b);
            }
        // relu + bias, repack as A2 fragments (k = m)
        unsigned A2[2][2][4];
        #pragma unroll
        for (int nt = 0; nt < 4; ++nt) {
            float2 b1v = *(const float2*)(b1_s + 8 * nt + 2 * qc);
            #pragma unroll
            for (int mt = 0; mt < 2; ++mt)
                #pragma unroll
                for (int hf = 0; hf < 2; ++hf) {
                    float v0 = fmaxf(ch[mt][nt][2 * hf]     + b1v.x, 0.f);
                    float v1 = fmaxf(ch[mt][nt][2 * hf + 1] + b1v.y, 0.f);
                    A2[mt][nt >> 1][(nt & 1) * 2 + hf] = packh2(v0, v1);
                }
        }
        // ---- MLP2: ls = hid @ W2 + b2 (N padded to 8) ----
        float cl[2][4];
        #pragma unroll
        for (int mt = 0; mt < 2; ++mt)
            #pragma unroll
            for (int i = 0; i < 4; ++i) cl[mt][i] = 0.f;
        #pragma unroll
        for (int kt = 0; kt < 2; ++kt) {
            unsigned b[2];
            b[0] = *(const unsigned*)(w2t_h + qr * 32 + 16 * kt + 2 * qc);
            b[1] = *(const unsigned*)(w2t_h + qr * 32 + 16 * kt + 2 * qc + 8);
            mma16816(cl[0], A2[0][kt], b);
            mma16816(cl[1], A2[1][kt], b);
        }
        // head: qc==0 lanes hold (ls0,ls1)=dloc, qc==1 lanes hold (ls2,ls3)->scale
        float2 b2v = *(const float2*)(b2_s + 2 * qc);
        #pragma unroll
        for (int mt = 0; mt < 2; ++mt)
            #pragma unroll
            for (int hf = 0; hf < 2; ++hf) {
                const int yi = hf + 2 * mt;
                float v0 = cl[mt][2 * hf]     + b2v.x;
                float v1 = cl[mt][2 * hf + 1] + b2v.y;
                float sp0 = softplus_(v0) + 0.001f;
                float sp1 = softplus_(v1) + 0.001f;
                float s0 = __shfl_sync(0xffffffffu, sp0, (lid & ~3) | 1);
                float s1 = __shfl_sync(0xffffffffu, sp1, (lid & ~3) | 1);
                if (owner) {
                    float yn0 = yown[2 * yi]     + v0 + s0 * xo[yi].x;
                    float yn1 = yown[2 * yi + 1] + v1 + s1 * xo[yi].y;
                    yown[2 * yi] = yn0; yown[2 * yi + 1] = yn1;
                    pown[2 * yi] *= s0; pown[2 * yi + 1] *= s1;
                    int rowg = rowbase + qr + 8 * yi;
                    *(float2*)(out + (size_t)rowg * 32 + 2 * t) = make_float2(yn0, yn1);
                }
            }
    }

    if (owner) {
        #pragma unroll
        for (int yi = 0; yi < 4; ++yi) {
            int rowg = rowbase + qr + 8 * yi;
            out[(size_t)Btot * 32 + rowg] =
                logf(fabsf(pown[2 * yi])) + logf(fabsf(pown[2 * yi + 1]));
        }
    }
}

extern "C" void kernel_launch(void* const* d_in, const int* in_sizes, int n_in,
                              void* d_out, int out_size)
{
    const float* x    = (const float*)d_in[0];
    const float* z    = (const float*)d_in[1];
    const float* W_ih = (const float*)d_in[2];
    const float* W_hh = (const float*)d_in[3];
    const float* b_ih = (const float*)d_in[4];
    const float* b_hh = (const float*)d_in[5];
    const float* W1   = (const float*)d_in[6];
    const float* b1   = (const float*)d_in[7];
    const float* W2   = (const float*)d_in[8];
    const float* b2   = (const float*)d_in[9];

    int B = in_sizes[1] / 64;   // z is (B, 64)

    flow_mma_kernel<<<B / EPB, BLK>>>(
        x, z, W_ih, W_hh, b_ih, b_hh, W1, b1, W2, b2, (float*)d_out, B);
}

// round 12
// speedup vs baseline: 1.8970x; 1.8951x over previous
#include <cuda_runtime.h>
#include <cuda_fp16.h>
#include <cstdint>

#define T_STEPS 16
#define BLK 256
#define EPB 256            // 8 warps x 32 batch rows per warp

#define WHH_LD 72          // padded row stride (halves): conflict-free banks
#define W1_LD  72
#define W2_LD  40

__device__ __forceinline__ float tanh_ap(float x) {
    float y; asm("tanh.approx.f32 %0, %1;" : "=f"(y) : "f"(x)); return y;
}
__device__ __forceinline__ float sigm(float x) {
    return fmaf(tanh_ap(0.5f * x), 0.5f, 0.5f);
}
__device__ __forceinline__ float softplus_(float x) {
    return fmaxf(x, 0.0f) + log1pf(__expf(-fabsf(x)));   // exact: sets rel_err
}
__device__ __forceinline__ unsigned packh2(float a, float b) {
    __half2 h = __floats2half2_rn(a, b);
    return *(unsigned*)&h;
}

// D = A(16x16 f16) @ B(16x8 f16) + C (f32), row.col
__device__ __forceinline__ void mma16816(float* c, const unsigned* a, const unsigned* b) {
    asm volatile("mma.sync.aligned.m16n8k16.row.col.f32.f16.f16.f32 "
                 "{%0,%1,%2,%3}, {%4,%5,%6,%7}, {%8,%9}, {%0,%1,%2,%3};"
                 : "+f"(c[0]), "+f"(c[1]), "+f"(c[2]), "+f"(c[3])
                 : "r"(a[0]), "r"(a[1]), "r"(a[2]), "r"(a[3]), "r"(b[0]), "r"(b[1]));
}

__global__ void __launch_bounds__(BLK)
flow_mma_kernel(const float* __restrict__ x, const float* __restrict__ z,
                const float* __restrict__ W_ih, const float* __restrict__ W_hh,
                const float* __restrict__ b_ih, const float* __restrict__ b_hh,
                const float* __restrict__ W1, const float* __restrict__ b1,
                const float* __restrict__ W2, const float* __restrict__ b2,
                float* __restrict__ out, int Btot)
{
    __shared__ __half whh_h[192 * WHH_LD];   // [j][k], padded
    __shared__ __half w1t_h[32 * W1_LD];     // [m][k] (W1 transposed), padded
    __shared__ __half w2t_h[8 * W2_LD];      // [n][k] (W2 transposed, n padded to 8)
    __shared__ float4 giw_s[192];            // {wih0, wih1, bias, bhh_n}
    __shared__ float  b1_s[32];
    __shared__ float  b2_s[8];               // padded

    const int tid = threadIdx.x;

    // ---- stage weights (fp16, padded rows) ----
    for (int i = tid; i < 12288; i += BLK) {
        int j = i >> 6, k = i & 63;
        whh_h[j * WHH_LD + k] = __float2half_rn(W_hh[i]);
    }
    for (int i = tid; i < 2048; i += BLK) {
        int m = i >> 6, k = i & 63;
        w1t_h[m * W1_LD + k] = __float2half_rn(W1[k * 32 + m]);
    }
    for (int i = tid; i < 256; i += BLK) {
        int n = i >> 5, k = i & 31;
        w2t_h[n * W2_LD + k] = (n < 4) ? __float2half_rn(W2[k * 4 + n]) : __float2half_rn(0.0f);
    }
    for (int j = tid; j < 192; j += BLK) {
        float bi = b_ih[j], bh = b_hh[j];
        giw_s[j] = (j < 128) ? make_float4(W_ih[2 * j], W_ih[2 * j + 1], bi + bh, 0.0f)
                             : make_float4(W_ih[2 * j], W_ih[2 * j + 1], bi, bh);
    }
    if (tid < 32) b1_s[tid] = b1[tid];
    if (tid < 8)  b2_s[tid] = (tid < 4) ? b2[tid] : 0.0f;
    __syncthreads();

    const int wid = tid >> 5, lid = tid & 31;
    const int qr = lid >> 2, qc = lid & 3;
    const int rowbase = blockIdx.x * EPB + wid * 32;   // warp's first batch row
    const bool owner = (qc == 0);

    // ---- hoist t-invariant W1 / W2 B-fragments into registers ----
    unsigned Bw1[4][4][2];                  // [kt][nt][reg]
    #pragma unroll
    for (int kt = 0; kt < 4; ++kt)
        #pragma unroll
        for (int nt = 0; nt < 4; ++nt) {
            int m = 8 * nt + qr;
            Bw1[kt][nt][0] = *(const unsigned*)(w1t_h + m * W1_LD + 16 * kt + 2 * qc);
            Bw1[kt][nt][1] = *(const unsigned*)(w1t_h + m * W1_LD + 16 * kt + 2 * qc + 8);
        }
    unsigned Bw2[2][2];                     // [kt][reg]
    #pragma unroll
    for (int kt = 0; kt < 2; ++kt) {
        Bw2[kt][0] = *(const unsigned*)(w2t_h + qr * W2_LD + 16 * kt + 2 * qc);
        Bw2[kt][1] = *(const unsigned*)(w2t_h + qr * W2_LD + 16 * kt + 2 * qc + 8);
    }

    // ---- A fragments = h (init from z), [Mtile][ktile][reg], f16x2 ----
    unsigned A[2][4][4];
    #pragma unroll
    for (int mt = 0; mt < 2; ++mt)
        #pragma unroll
        for (int kt = 0; kt < 4; ++kt)
            #pragma unroll
            for (int rg = 0; rg < 4; ++rg) {
                int row = rowbase + 16 * mt + qr + 8 * (rg & 1);
                int k = 2 * qc + 8 * (rg >> 1) + 16 * kt;
                float2 v = *(const float2*)(z + (size_t)row * 64 + k);
                A[mt][kt][rg] = packh2(v.x, v.y);
            }

    // owner-lane per-row state: rows rowbase + qr + 8*yi, yi = 0..3
    float yown[8] = {0.f, 0.f, 0.f, 0.f, 0.f, 0.f, 0.f, 0.f};
    float pown[8] = {1.f, 1.f, 1.f, 1.f, 1.f, 1.f, 1.f, 1.f};

    #pragma unroll 1
    for (int t = 0; t < T_STEPS; ++t) {
        // broadcast y_prev of the 4 rows this lane epilogues (owner lane = 4*qr)
        float yp[8];
        #pragma unroll
        for (int yi = 0; yi < 4; ++yi) {
            yp[2 * yi]     = __shfl_sync(0xffffffffu, yown[2 * yi],     4 * qr);
            yp[2 * yi + 1] = __shfl_sync(0xffffffffu, yown[2 * yi + 1], 4 * qr);
        }
        // x_t for the quad's rows (same address across quad -> dedup'd)
        float2 xo[4];
        #pragma unroll
        for (int yi = 0; yi < 4; ++yi)
            xo[yi] = *(const float2*)(x + (size_t)(rowbase + qr + 8 * yi) * 32 + 2 * t);

        // ---- GRU: gh = h @ W_hh^T via HMMA, gates in epilogue ----
        unsigned Anew[2][4][4];
        #pragma unroll
        for (int jt = 0; jt < 8; ++jt) {
            float c[3][2][4];
            #pragma unroll
            for (int g = 0; g < 3; ++g)
                #pragma unroll
                for (int mt = 0; mt < 2; ++mt)
                    #pragma unroll
                    for (int i = 0; i < 4; ++i) c[g][mt][i] = 0.f;

            #pragma unroll
            for (int kt = 0; kt < 4; ++kt)
                #pragma unroll
                for (int g = 0; g < 3; ++g) {
                    int j = 8 * (jt + 8 * g) + qr;      // B col n = qr
                    unsigned b[2];
                    b[0] = *(const unsigned*)(whh_h + j * WHH_LD + 16 * kt + 2 * qc);
                    b[1] = *(const unsigned*)(whh_h + j * WHH_LD + 16 * kt + 2 * qc + 8);
                    mma16816(c[g][0], A[0][kt], b);
                    mma16816(c[g][1], A[1][kt], b);
                }

            const int j0 = 8 * jt + 2 * qc;
            const float4 gr0 = giw_s[j0],       gr1 = giw_s[j0 + 1];
            const float4 gz0 = giw_s[64 + j0],  gz1 = giw_s[64 + j0 + 1];
            const float4 gn0 = giw_s[128 + j0], gn1 = giw_s[128 + j0 + 1];

            #pragma unroll
            for (int mt = 0; mt < 2; ++mt)
                #pragma unroll
                for (int hf = 0; hf < 2; ++hf) {
                    const int yi = hf + 2 * mt;
                    const float y0 = yp[2 * yi], y1 = yp[2 * yi + 1];
                    // col 0
                    float r0 = sigm(fmaf(y1, gr0.y, fmaf(y0, gr0.x, gr0.z)) + c[0][mt][2 * hf]);
                    float u0 = sigm(fmaf(y1, gz0.y, fmaf(y0, gz0.x, gz0.z)) + c[1][mt][2 * hf]);
                    float n0 = tanh_ap(fmaf(r0, c[2][mt][2 * hf] + gn0.w,
                                            fmaf(y1, gn0.y, fmaf(y0, gn0.x, gn0.z))));
                    // col 1
                    float r1 = sigm(fmaf(y1, gr1.y, fmaf(y0, gr1.x, gr1.z)) + c[0][mt][2 * hf + 1]);
                    float u1 = sigm(fmaf(y1, gz1.y, fmaf(y0, gz1.x, gz1.z)) + c[1][mt][2 * hf + 1]);
                    float n1 = tanh_ap(fmaf(r1, c[2][mt][2 * hf + 1] + gn1.w,
                                            fmaf(y1, gn1.y, fmaf(y0, gn1.x, gn1.z))));
                    // hold = old h at same fragment slot
                    unsigned au = A[mt][jt >> 1][(jt & 1) * 2 + hf];
                    __half2 hh = *(__half2*)&au;
                    float h0 = fmaf(u0, __half2float(hh.x) - n0, n0);
                    float h1 = fmaf(u1, __half2float(hh.y) - n1, n1);
                    Anew[mt][jt >> 1][(jt & 1) * 2 + hf] = packh2(h0, h1);
                }
        }
        // commit h_new
        #pragma unroll
        for (int mt = 0; mt < 2; ++mt)
            #pragma unroll
            for (int kt = 0; kt < 4; ++kt)
                #pragma unroll
                for (int rg = 0; rg < 4; ++rg) A[mt][kt][rg] = Anew[mt][kt][rg];

        // ---- MLP1: hid = relu(h_new @ W1 + b1) via HMMA (B-frags in regs) ----
        float ch[2][4][4];
        #pragma unroll
        for (int mt = 0; mt < 2; ++mt)
            #pragma unroll
            for (int nt = 0; nt < 4; ++nt)
                #pragma unroll
                for (int i = 0; i < 4; ++i) ch[mt][nt][i] = 0.f;
        #pragma unroll
        for (int kt = 0; kt < 4; ++kt)
            #pragma unroll
            for (int nt = 0; nt < 4; ++nt) {
                mma16816(ch[0][nt], A[0][kt], Bw1[kt][nt]);
                mma16816(ch[1][nt], A[1][kt], Bw1[kt][nt]);
            }
        // relu + bias, repack as A2 fragments (k = m)
        unsigned A2[2][2][4];
        #pragma unroll
        for (int nt = 0; nt < 4; ++nt) {
            float2 b1v = *(const float2*)(b1_s + 8 * nt + 2 * qc);
            #pragma unroll
            for (int mt = 0; mt < 2; ++mt)
                #pragma unroll
                for (int hf = 0; hf < 2; ++hf) {
                    float v0 = fmaxf(ch[mt][nt][2 * hf]     + b1v.x, 0.f);
                    float v1 = fmaxf(ch[mt][nt][2 * hf + 1] + b1v.y, 0.f);
                    A2[mt][nt >> 1][(nt & 1) * 2 + hf] = packh2(v0, v1);
                }
        }
        // ---- MLP2: ls = hid @ W2 + b2 (N padded to 8, B-frags in regs) ----
        float cl[2][4];
        #pragma unroll
        for (int mt = 0; mt < 2; ++mt)
            #pragma unroll
            for (int i = 0; i < 4; ++i) cl[mt][i] = 0.f;
        #pragma unroll
        for (int kt = 0; kt < 2; ++kt) {
            mma16816(cl[0], A2[0][kt], Bw2[kt]);
            mma16816(cl[1], A2[1][kt], Bw2[kt]);
        }
        // head: qc==0 lanes hold (ls0,ls1)=dloc, qc==1 lanes hold (ls2,ls3)->scale
        float2 b2v = *(const float2*)(b2_s + 2 * qc);
        #pragma unroll
        for (int mt = 0; mt < 2; ++mt)
            #pragma unroll
            for (int hf = 0; hf < 2; ++hf) {
                const int yi = hf + 2 * mt;
                float v0 = cl[mt][2 * hf]     + b2v.x;
                float v1 = cl[mt][2 * hf + 1] + b2v.y;
                float sp0 = softplus_(v0) + 0.001f;
                float sp1 = softplus_(v1) + 0.001f;
                float s0 = __shfl_sync(0xffffffffu, sp0, (lid & ~3) | 1);
                float s1 = __shfl_sync(0xffffffffu, sp1, (lid & ~3) | 1);
                if (owner) {
                    float yn0 = yown[2 * yi]     + v0 + s0 * xo[yi].x;
                    float yn1 = yown[2 * yi + 1] + v1 + s1 * xo[yi].y;
                    yown[2 * yi] = yn0; yown[2 * yi + 1] = yn1;
                    pown[2 * yi] *= s0; pown[2 * yi + 1] *= s1;
                    int rowg = rowbase + qr + 8 * yi;
                    *(float2*)(out + (size_t)rowg * 32 + 2 * t) = make_float2(yn0, yn1);
                }
            }
    }

    if (owner) {
        #pragma unroll
        for (int yi = 0; yi < 4; ++yi) {
            int rowg = rowbase + qr + 8 * yi;
            out[(size_t)Btot * 32 + rowg] =
                logf(fabsf(pown[2 * yi])) + logf(fabsf(pown[2 * yi + 1]));
        }
    }
}

extern "C" void kernel_launch(void* const* d_in, const int* in_sizes, int n_in,
                              void* d_out, int out_size)
{
    const float* x    = (const float*)d_in[0];
    const float* z    = (const float*)d_in[1];
    const float* W_ih = (const float*)d_in[2];
    const float* W_hh = (const float*)d_in[3];
    const float* b_ih = (const float*)d_in[4];
    const float* b_hh = (const float*)d_in[5];
    const float* W1   = (const float*)d_in[6];
    const float* b1   = (const float*)d_in[7];
    const float* W2   = (const float*)d_in[8];
    const float* b2   = (const float*)d_in[9];

    int B = in_sizes[1] / 64;   // z is (B, 64)

    flow_mma_kernel<<<B / EPB, BLK>>>(
        x, z, W_ih, W_hh, b_ih, b_hh, W1, b1, W2, b2, (float*)d_out, B);
}

// round 13
// speedup vs baseline: 2.2568x; 1.1897x over previous
#include <cuda_runtime.h>
#include <cuda_fp16.h>
#include <cstdint>

#define T_STEPS 16
#define BLK 128
#define EPB 128            // 4 warps x 32 batch rows per warp

#define WHH_LD 72          // padded row stride (halves): conflict-free banks
#define W1_LD  72
#define W2_LD  40

__device__ __forceinline__ float softplus_(float x) {
    return fmaxf(x, 0.0f) + log1pf(__expf(-fabsf(x)));   // exact: sets rel_err
}
__device__ __forceinline__ unsigned packh2(float a, float b) {
    __half2 h = __floats2half2_rn(a, b);
    return *(unsigned*)&h;
}
// pack two f32 -> f16x2 (lo = a, hi = b)
__device__ __forceinline__ __half2 pk2(float a, float b) {
    __half2 d;
    asm("cvt.rn.f16x2.f32 %0, %2, %1;" : "=r"(*(unsigned*)&d) : "f"(a), "f"(b));
    return d;
}
__device__ __forceinline__ __half2 tanh2(__half2 x) {
    __half2 y;
    asm("tanh.approx.f16x2 %0, %1;" : "=r"(*(unsigned*)&y) : "r"(*(unsigned*)&x));
    return y;
}
__device__ __forceinline__ __half2 sigm2(__half2 x) {
    const __half2 hlf = __floats2half2_rn(0.5f, 0.5f);
    return __hfma2(tanh2(__hmul2(x, hlf)), hlf, hlf);
}

// D = A(16x16 f16) @ B(16x8 f16) + C (f32), row.col
__device__ __forceinline__ void mma16816(float* c, const unsigned* a, const unsigned* b) {
    asm volatile("mma.sync.aligned.m16n8k16.row.col.f32.f16.f16.f32 "
                 "{%0,%1,%2,%3}, {%4,%5,%6,%7}, {%8,%9}, {%0,%1,%2,%3};"
                 : "+f"(c[0]), "+f"(c[1]), "+f"(c[2]), "+f"(c[3])
                 : "r"(a[0]), "r"(a[1]), "r"(a[2]), "r"(a[3]), "r"(b[0]), "r"(b[1]));
}

__global__ void __launch_bounds__(BLK)
flow_mma_kernel(const float* __restrict__ x, const float* __restrict__ z,
                const float* __restrict__ W_ih, const float* __restrict__ W_hh,
                const float* __restrict__ b_ih, const float* __restrict__ b_hh,
                const float* __restrict__ W1, const float* __restrict__ b1,
                const float* __restrict__ W2, const float* __restrict__ b2,
                float* __restrict__ out, int Btot)
{
    __shared__ __half whh_h[192 * WHH_LD];   // [j][k], padded
    __shared__ __half w1t_h[32 * W1_LD];     // [m][k] (W1 transposed), padded
    __shared__ __half w2t_h[8 * W2_LD];      // [n][k] (W2 transposed, n padded to 8)
    __shared__ float4 giw_s[192];            // {wih0, wih1, bias, bhh_n}
    __shared__ float  b1_s[32];
    __shared__ float  b2_s[8];               // padded

    const int tid = threadIdx.x;

    // ---- stage weights (fp16, padded rows) ----
    for (int i = tid; i < 12288; i += BLK) {
        int j = i >> 6, k = i & 63;
        whh_h[j * WHH_LD + k] = __float2half_rn(W_hh[i]);
    }
    for (int i = tid; i < 2048; i += BLK) {
        int m = i >> 6, k = i & 63;
        w1t_h[m * W1_LD + k] = __float2half_rn(W1[k * 32 + m]);
    }
    for (int i = tid; i < 256; i += BLK) {
        int n = i >> 5, k = i & 31;
        w2t_h[n * W2_LD + k] = (n < 4) ? __float2half_rn(W2[k * 4 + n]) : __float2half_rn(0.0f);
    }
    for (int j = tid; j < 192; j += BLK) {
        float bi = b_ih[j], bh = b_hh[j];
        giw_s[j] = (j < 128) ? make_float4(W_ih[2 * j], W_ih[2 * j + 1], bi + bh, 0.0f)
                             : make_float4(W_ih[2 * j], W_ih[2 * j + 1], bi, bh);
    }
    if (tid < 32) b1_s[tid] = b1[tid];
    if (tid < 8)  b2_s[tid] = (tid < 4) ? b2[tid] : 0.0f;
    __syncthreads();

    const int wid = tid >> 5, lid = tid & 31;
    const int qr = lid >> 2, qc = lid & 3;
    const int rowbase = blockIdx.x * EPB + wid * 32;   // warp's first batch row
    const bool owner = (qc == 0);

    // ---- hoist t-invariant W1 / W2 B-fragments into registers ----
    unsigned Bw1[4][4][2];                  // [kt][nt][reg]
    #pragma unroll
    for (int kt = 0; kt < 4; ++kt)
        #pragma unroll
        for (int nt = 0; nt < 4; ++nt) {
            int m = 8 * nt + qr;
            Bw1[kt][nt][0] = *(const unsigned*)(w1t_h + m * W1_LD + 16 * kt + 2 * qc);
            Bw1[kt][nt][1] = *(const unsigned*)(w1t_h + m * W1_LD + 16 * kt + 2 * qc + 8);
        }
    unsigned Bw2[2][2];                     // [kt][reg]
    #pragma unroll
    for (int kt = 0; kt < 2; ++kt) {
        Bw2[kt][0] = *(const unsigned*)(w2t_h + qr * W2_LD + 16 * kt + 2 * qc);
        Bw2[kt][1] = *(const unsigned*)(w2t_h + qr * W2_LD + 16 * kt + 2 * qc + 8);
    }
    // per-lane b1 pairs as f16x2 (for MLP1 epilogue)
    __half2 b1h[4];
    #pragma unroll
    for (int nt = 0; nt < 4; ++nt)
        b1h[nt] = pk2(b1_s[8 * nt + 2 * qc], b1_s[8 * nt + 2 * qc + 1]);

    // ---- A fragments = h (init from z), [Mtile][ktile][reg], f16x2 ----
    unsigned A[2][4][4];
    #pragma unroll
    for (int mt = 0; mt < 2; ++mt)
        #pragma unroll
        for (int kt = 0; kt < 4; ++kt)
            #pragma unroll
            for (int rg = 0; rg < 4; ++rg) {
                int row = rowbase + 16 * mt + qr + 8 * (rg & 1);
                int k = 2 * qc + 8 * (rg >> 1) + 16 * kt;
                float2 v = *(const float2*)(z + (size_t)row * 64 + k);
                A[mt][kt][rg] = packh2(v.x, v.y);
            }

    // owner-lane per-row state: rows rowbase + qr + 8*yi, yi = 0..3
    float yown[8] = {0.f, 0.f, 0.f, 0.f, 0.f, 0.f, 0.f, 0.f};
    float pown[8] = {1.f, 1.f, 1.f, 1.f, 1.f, 1.f, 1.f, 1.f};

    #pragma unroll 1
    for (int t = 0; t < T_STEPS; ++t) {
        // broadcast y_prev of the 4 rows this lane epilogues (owner lane = 4*qr)
        float yp[8];
        #pragma unroll
        for (int yi = 0; yi < 4; ++yi) {
            yp[2 * yi]     = __shfl_sync(0xffffffffu, yown[2 * yi],     4 * qr);
            yp[2 * yi + 1] = __shfl_sync(0xffffffffu, yown[2 * yi + 1], 4 * qr);
        }
        // x_t for the quad's rows (same address across quad -> dedup'd)
        float2 xo[4];
        #pragma unroll
        for (int yi = 0; yi < 4; ++yi)
            xo[yi] = *(const float2*)(x + (size_t)(rowbase + qr + 8 * yi) * 32 + 2 * t);

        // ---- GRU: gh = h @ W_hh^T via HMMA, f16x2 gate epilogue ----
        unsigned Anew[2][4][4];
        #pragma unroll
        for (int jt = 0; jt < 8; ++jt) {
            float c[3][2][4];
            #pragma unroll
            for (int g = 0; g < 3; ++g)
                #pragma unroll
                for (int mt = 0; mt < 2; ++mt)
                    #pragma unroll
                    for (int i = 0; i < 4; ++i) c[g][mt][i] = 0.f;

            #pragma unroll
            for (int kt = 0; kt < 4; ++kt)
                #pragma unroll
                for (int g = 0; g < 3; ++g) {
                    int j = 8 * (jt + 8 * g) + qr;      // B col n = qr
                    unsigned b[2];
                    b[0] = *(const unsigned*)(whh_h + j * WHH_LD + 16 * kt + 2 * qc);
                    b[1] = *(const unsigned*)(whh_h + j * WHH_LD + 16 * kt + 2 * qc + 8);
                    mma16816(c[g][0], A[0][kt], b);
                    mma16816(c[g][1], A[1][kt], b);
                }

            const int j0 = 8 * jt + 2 * qc;
            const float4 gr0 = giw_s[j0],       gr1 = giw_s[j0 + 1];
            const float4 gz0 = giw_s[64 + j0],  gz1 = giw_s[64 + j0 + 1];
            const float4 gn0 = giw_s[128 + j0], gn1 = giw_s[128 + j0 + 1];
            const __half2 bhn2 = pk2(gn0.w, gn1.w);

            #pragma unroll
            for (int mt = 0; mt < 2; ++mt)
                #pragma unroll
                for (int hf = 0; hf < 2; ++hf) {
                    const int yi = hf + 2 * mt;
                    const float y0 = yp[2 * yi], y1 = yp[2 * yi + 1];
                    // fp32 gi terms (2 fma per col), then pack to f16x2
                    __half2 gih_r = pk2(fmaf(y1, gr0.y, fmaf(y0, gr0.x, gr0.z)),
                                        fmaf(y1, gr1.y, fmaf(y0, gr1.x, gr1.z)));
                    __half2 gih_z = pk2(fmaf(y1, gz0.y, fmaf(y0, gz0.x, gz0.z)),
                                        fmaf(y1, gz1.y, fmaf(y0, gz1.x, gz1.z)));
                    __half2 gih_n = pk2(fmaf(y1, gn0.y, fmaf(y0, gn0.x, gn0.z)),
                                        fmaf(y1, gn1.y, fmaf(y0, gn1.x, gn1.z)));
                    // C fragments as f16x2 (two adjacent cols)
                    __half2 cr = pk2(c[0][mt][2 * hf], c[0][mt][2 * hf + 1]);
                    __half2 cz = pk2(c[1][mt][2 * hf], c[1][mt][2 * hf + 1]);
                    __half2 cn = pk2(c[2][mt][2 * hf], c[2][mt][2 * hf + 1]);
                    __half2 r = sigm2(__hadd2(gih_r, cr));
                    __half2 u = sigm2(__hadd2(gih_z, cz));
                    __half2 hn = __hadd2(cn, bhn2);
                    __half2 n = tanh2(__hfma2(r, hn, gih_n));
                    // hold = old h at same fragment slot (already f16x2)
                    unsigned au = A[mt][jt >> 1][(jt & 1) * 2 + hf];
                    __half2 hold = *(__half2*)&au;
                    __half2 hnew = __hfma2(u, __hsub2(hold, n), n);
                    Anew[mt][jt >> 1][(jt & 1) * 2 + hf] = *(unsigned*)&hnew;
                }
        }
        // commit h_new
        #pragma unroll
        for (int mt = 0; mt < 2; ++mt)
            #pragma unroll
            for (int kt = 0; kt < 4; ++kt)
                #pragma unroll
                for (int rg = 0; rg < 4; ++rg) A[mt][kt][rg] = Anew[mt][kt][rg];

        // ---- MLP1: hid = relu(h_new @ W1 + b1) via HMMA (B-frags in regs) ----
        float ch[2][4][4];
        #pragma unroll
        for (int mt = 0; mt < 2; ++mt)
            #pragma unroll
            for (int nt = 0; nt < 4; ++nt)
                #pragma unroll
                for (int i = 0; i < 4; ++i) ch[mt][nt][i] = 0.f;
        #pragma unroll
        for (int kt = 0; kt < 4; ++kt)
            #pragma unroll
            for (int nt = 0; nt < 4; ++nt) {
                mma16816(ch[0][nt], A[0][kt], Bw1[kt][nt]);
                mma16816(ch[1][nt], A[1][kt], Bw1[kt][nt]);
            }
        // relu + bias in f16x2, repack as A2 fragments (k = m)
        unsigned A2[2][2][4];
        const __half2 zero2 = __floats2half2_rn(0.f, 0.f);
        #pragma unroll
        for (int nt = 0; nt < 4; ++nt) {
            #pragma unroll
            for (int mt = 0; mt < 2; ++mt)
                #pragma unroll
                for (int hf = 0; hf < 2; ++hf) {
                    __half2 v = __hmax2(__hadd2(pk2(ch[mt][nt][2 * hf],
                                                    ch[mt][nt][2 * hf + 1]), b1h[nt]), zero2);
                    A2[mt][nt >> 1][(nt & 1) * 2 + hf] = *(unsigned*)&v;
                }
        }
        // ---- MLP2: ls = hid @ W2 + b2 (N padded to 8, B-frags in regs) ----
        float cl[2][4];
        #pragma unroll
        for (int mt = 0; mt < 2; ++mt)
            #pragma unroll
            for (int i = 0; i < 4; ++i) cl[mt][i] = 0.f;
        #pragma unroll
        for (int kt = 0; kt < 2; ++kt) {
            mma16816(cl[0], A2[0][kt], Bw2[kt]);
            mma16816(cl[1], A2[1][kt], Bw2[kt]);
        }
        // head: qc==0 lanes hold (ls0,ls1)=dloc, qc==1 lanes hold (ls2,ls3)->scale
        float2 b2v = *(const float2*)(b2_s + 2 * qc);
        #pragma unroll
        for (int mt = 0; mt < 2; ++mt)
            #pragma unroll
            for (int hf = 0; hf < 2; ++hf) {
                const int yi = hf + 2 * mt;
                float v0 = cl[mt][2 * hf]     + b2v.x;
                float v1 = cl[mt][2 * hf + 1] + b2v.y;
                float sp0 = softplus_(v0) + 0.001f;
                float sp1 = softplus_(v1) + 0.001f;
                float s0 = __shfl_sync(0xffffffffu, sp0, (lid & ~3) | 1);
                float s1 = __shfl_sync(0xffffffffu, sp1, (lid & ~3) | 1);
                if (owner) {
                    float yn0 = yown[2 * yi]     + v0 + s0 * xo[yi].x;
                    float yn1 = yown[2 * yi + 1] + v1 + s1 * xo[yi].y;
                    yown[2 * yi] = yn0; yown[2 * yi + 1] = yn1;
                    pown[2 * yi] *= s0; pown[2 * yi + 1] *= s1;
                    int rowg = rowbase + qr + 8 * yi;
                    *(float2*)(out + (size_t)rowg * 32 + 2 * t) = make_float2(yn0, yn1);
                }
            }
    }

    if (owner) {
        #pragma unroll
        for (int yi = 0; yi < 4; ++yi) {
            int rowg = rowbase + qr + 8 * yi;
            out[(size_t)Btot * 32 + rowg] =
                logf(fabsf(pown[2 * yi])) + logf(fabsf(pown[2 * yi + 1]));
        }
    }
}

extern "C" void kernel_launch(void* const* d_in, const int* in_sizes, int n_in,
                              void* d_out, int out_size)
{
    const float* x    = (const float*)d_in[0];
    const float* z    = (const float*)d_in[1];
    const float* W_ih = (const float*)d_in[2];
    const float* W_hh = (const float*)d_in[3];
    const float* b_ih = (const float*)d_in[4];
    const float* b_hh = (const float*)d_in[5];
    const float* W1   = (const float*)d_in[6];
    const float* b1   = (const float*)d_in[7];
    const float* W2   = (const float*)d_in[8];
    const float* b2   = (const float*)d_in[9];

    int B = in_sizes[1] / 64;   // z is (B, 64)

    flow_mma_kernel<<<B / EPB, BLK>>>(
        x, z, W_ih, W_hh, b_ih, b_hh, W1, b1, W2, b2, (float*)d_out, B);
}